// round 2
// baseline (speedup 1.0000x reference)
#include <cuda_runtime.h>
#include <cstdint>

#define T_STEPS 512
#define BATCH   64
#define IN_DIM  256
#define HID     512
#define OUT_DIM 256
#define G4      2048   // 4*HID

#define NCTA     128
#define RTHREADS 256

#define SW_STRIDE 520              // 512 + 8 pad
#define SH_STRIDE 68               // 64 + 4 pad
#define SW_FLOATS (16 * SW_STRIDE) // 8320
#define SH_CHUNK  (64 * SH_STRIDE) // 4352 floats per (half,buf) chunk
#define SH_BASE   SW_FLOATS
#define SRED_BASE (SH_BASE + 4 * SH_CHUNK)   // 25728
#define SMEM_FLOATS (SRED_BASE + 128 * 8)    // 26752
#define SMEM_BYTES  (SMEM_FLOATS * 4)        // 107008

#define OFF_H ((size_t)T_STEPS * BATCH * OUT_DIM)       // 8388608
#define OFF_C (OFF_H + (size_t)BATCH * HID)             // 8421376

// ---------------- persistent device state ----------------
__device__ float    g_xg[(size_t)T_STEPS * BATCH * G4];   // x-gate precompute (256MB)
__device__ float    g_hs[(size_t)T_STEPS * BATCH * HID];  // h history (64MB)
__device__ float    g_bsum[G4];
__device__ unsigned g_bar;

// ---------------- reset (per replay) ----------------
__global__ void reset_kernel(const float* __restrict__ b_ih,
                             const float* __restrict__ b_hh) {
    int idx = blockIdx.x * blockDim.x + threadIdx.x;
    if (idx == 0) g_bar = 0u;
    if (idx < G4) g_bsum[idx] = b_ih[idx] + b_hh[idx];
}

// ---------------- generic C[m][n] = sum_k A[m][k]*B[n][k] + bias[n] ----------
// 64x64 tile, BK=16, 256 threads, 4x4 microtile.
__global__ __launch_bounds__(256) void gemm_tn64(
    const float* __restrict__ A, const float* __restrict__ Bm,
    const float* __restrict__ bias, float* __restrict__ C,
    int M, int N, int K)
{
    __shared__ float As[16][64];
    __shared__ float Bs[16][64];
    const int tid = threadIdx.x;
    const int m0 = blockIdx.y * 64, n0 = blockIdx.x * 64;
    const int r  = tid >> 2;
    const int kq = (tid & 3) << 2;
    const int tx = tid & 15, ty = tid >> 4;

    float acc[4][4] = {};

    for (int k0 = 0; k0 < K; k0 += 16) {
        float4 av = *(const float4*)(A  + (size_t)(m0 + r) * K + k0 + kq);
        float4 bv = *(const float4*)(Bm + (size_t)(n0 + r) * K + k0 + kq);
        As[kq + 0][r] = av.x; As[kq + 1][r] = av.y;
        As[kq + 2][r] = av.z; As[kq + 3][r] = av.w;
        Bs[kq + 0][r] = bv.x; Bs[kq + 1][r] = bv.y;
        Bs[kq + 2][r] = bv.z; Bs[kq + 3][r] = bv.w;
        __syncthreads();
        #pragma unroll
        for (int kk = 0; kk < 16; kk++) {
            float4 a4 = *(const float4*)&As[kk][ty << 2];
            float4 b4 = *(const float4*)&Bs[kk][tx << 2];
            float a[4] = {a4.x, a4.y, a4.z, a4.w};
            float b[4] = {b4.x, b4.y, b4.z, b4.w};
            #pragma unroll
            for (int i2 = 0; i2 < 4; i2++)
                #pragma unroll
                for (int j2 = 0; j2 < 4; j2++)
                    acc[i2][j2] = fmaf(a[i2], b[j2], acc[i2][j2]);
        }
        __syncthreads();
    }

    const int ncol = n0 + (tx << 2);
    float4 bb = *(const float4*)(bias + ncol);
    #pragma unroll
    for (int i2 = 0; i2 < 4; i2++) {
        int mrow = m0 + (ty << 2) + i2;
        float4 o;
        o.x = acc[i2][0] + bb.x;
        o.y = acc[i2][1] + bb.y;
        o.z = acc[i2][2] + bb.z;
        o.w = acc[i2][3] + bb.w;
        *(float4*)(C + (size_t)mrow * N + ncol) = o;
    }
}

// ---------------- persistent recurrent kernel ----------------
__device__ __forceinline__ float sigf(float x) { return 1.f / (1.f + __expf(-x)); }

__device__ __forceinline__ void cp_async16(float* dst_smem, const float* src) {
    unsigned d = (unsigned)__cvta_generic_to_shared(dst_smem);
    asm volatile("cp.async.cg.shared.global [%0], [%1], 16;" :: "r"(d), "l"(src) : "memory");
}

__global__ void __launch_bounds__(RTHREADS, 1)
lstm_recurrent(const float* __restrict__ W_hh, float* __restrict__ out)
{
    extern __shared__ float smem[];
    const int tid = threadIdx.x;
    const int j0  = blockIdx.x << 2;    // this CTA owns h columns [j0, j0+4)
    const int hk  = tid >> 7;           // K-half: 0 -> k in [0,256), 1 -> [256,512)
    const int t2  = tid & 127;
    const int bq  = t2 & 31;            // handles batch rows bq and bq+32
    const int ii  = t2 >> 5;            // which of the 4 owned h columns
    const int j   = j0 + ii;

    // --- load W_hh slice into smem: rows {q*512 + j0 + i}, r = q*4 + i ---
    #pragma unroll
    for (int u = 0; u < 8; u++) {
        int f4 = u * 256 + tid;          // 0..2047 float4s
        int rr = f4 >> 7;                // 0..15
        int kk = (f4 & 127) << 2;        // 0..508
        int q  = rr >> 2, iw = rr & 3;
        float4 v = *(const float4*)(W_hh + (size_t)(q * HID + j0 + iw) * HID + kk);
        *(float4*)(smem + rr * SW_STRIDE + kk) = v;
    }
    __syncthreads();

    float c0 = 0.f, c1 = 0.f;

    for (int t = 0; t < T_STEPS; t++) {
        float acc[2][4] = {{0.f, 0.f, 0.f, 0.f}, {0.f, 0.f, 0.f, 0.f}};

        // x-gate contributions for this thread's outputs (only hk==0 needs them)
        float xg[2][4];
        if (hk == 0) {
            const float* xp = g_xg + (size_t)t * BATCH * G4;
            #pragma unroll
            for (int q = 0; q < 4; q++) {
                xg[0][q] = xp[(size_t)bq * G4        + q * HID + j];
                xg[1][q] = xp[(size_t)(bq + 32) * G4 + q * HID + j];
            }
        }

        if (t > 0) {
            const float* hsrc = g_hs + (size_t)(t - 1) * (BATCH * HID);

            // prefetch chunk 0 into buf 0 (each K-half loads its own chunks)
            {
                float* dst = smem + SH_BASE + (hk * 2 + 0) * SH_CHUNK;
                const int kbase = hk * 256;
                #pragma unroll
                for (int u = 0; u < 8; u++) {
                    int f4 = u * 128 + t2;
                    int b  = f4 >> 4;
                    int kq = (f4 & 15) << 2;
                    cp_async16(dst + b * SH_STRIDE + kq,
                               hsrc + (size_t)b * HID + kbase + kq);
                }
                asm volatile("cp.async.commit_group;" ::: "memory");
            }

            #pragma unroll
            for (int ci = 0; ci < 4; ci++) {
                if (ci < 3) {
                    const int buf = (ci + 1) & 1;
                    float* dst = smem + SH_BASE + (hk * 2 + buf) * SH_CHUNK;
                    const int kbase = hk * 256 + (ci + 1) * 64;
                    #pragma unroll
                    for (int u = 0; u < 8; u++) {
                        int f4 = u * 128 + t2;
                        int b  = f4 >> 4;
                        int kq = (f4 & 15) << 2;
                        cp_async16(dst + b * SH_STRIDE + kq,
                                   hsrc + (size_t)b * HID + kbase + kq);
                    }
                    asm volatile("cp.async.commit_group;" ::: "memory");
                    asm volatile("cp.async.wait_group 1;" ::: "memory");
                } else {
                    asm volatile("cp.async.wait_group 0;" ::: "memory");
                }
                __syncthreads();

                const float* shp = smem + SH_BASE + (hk * 2 + (ci & 1)) * SH_CHUNK;
                const int kw = hk * 256 + ci * 64;   // k offset into sW rows
                #pragma unroll
                for (int kk = 0; kk < 64; kk += 4) {
                    float4 h0 = *(const float4*)(shp + bq * SH_STRIDE + kk);
                    float4 h1 = *(const float4*)(shp + (bq + 32) * SH_STRIDE + kk);
                    #pragma unroll
                    for (int q = 0; q < 4; q++) {
                        float4 w = *(const float4*)(smem + (q * 4 + ii) * SW_STRIDE + kw + kk);
                        acc[0][q] = fmaf(h0.x, w.x, acc[0][q]);
                        acc[0][q] = fmaf(h0.y, w.y, acc[0][q]);
                        acc[0][q] = fmaf(h0.z, w.z, acc[0][q]);
                        acc[0][q] = fmaf(h0.w, w.w, acc[0][q]);
                        acc[1][q] = fmaf(h1.x, w.x, acc[1][q]);
                        acc[1][q] = fmaf(h1.y, w.y, acc[1][q]);
                        acc[1][q] = fmaf(h1.z, w.z, acc[1][q]);
                        acc[1][q] = fmaf(h1.w, w.w, acc[1][q]);
                    }
                }
                __syncthreads();
            }
        }

        // --- combine K-halves: hk1 publishes partials, hk0 finishes cell ---
        if (hk == 1) {
            float* rp = smem + SRED_BASE + t2 * 8;
            #pragma unroll
            for (int bb = 0; bb < 2; bb++)
                #pragma unroll
                for (int q = 0; q < 4; q++)
                    rp[bb * 4 + q] = acc[bb][q];
        }
        __syncthreads();

        if (hk == 0) {
            const float* rp = smem + SRED_BASE + t2 * 8;
            #pragma unroll
            for (int bb = 0; bb < 2; bb++)
                #pragma unroll
                for (int q = 0; q < 4; q++)
                    acc[bb][q] += rp[bb * 4 + q];

            // gates (PyTorch order i, f, g, o)
            float i0 = sigf (acc[0][0] + xg[0][0]);
            float f0 = sigf (acc[0][1] + xg[0][1]);
            float gg0 = tanhf(acc[0][2] + xg[0][2]);
            float o0 = sigf (acc[0][3] + xg[0][3]);
            c0 = f0 * c0 + i0 * gg0;
            float h0n = o0 * tanhf(c0);

            float i1 = sigf (acc[1][0] + xg[1][0]);
            float f1 = sigf (acc[1][1] + xg[1][1]);
            float gg1 = tanhf(acc[1][2] + xg[1][2]);
            float o1 = sigf (acc[1][3] + xg[1][3]);
            c1 = f1 * c1 + i1 * gg1;
            float h1n = o1 * tanhf(c1);

            float* hdst = g_hs + (size_t)t * (BATCH * HID);
            hdst[(size_t)bq * HID + j]        = h0n;
            hdst[(size_t)(bq + 32) * HID + j] = h1n;

            if (t == T_STEPS - 1) {
                out[OFF_H + (size_t)bq * HID + j]        = h0n;
                out[OFF_H + (size_t)(bq + 32) * HID + j] = h1n;
                out[OFF_C + (size_t)bq * HID + j]        = c0;
                out[OFF_C + (size_t)(bq + 32) * HID + j] = c1;
            }
        }
        __syncthreads();

        // --- grid-wide barrier (all 128 CTAs co-resident) ---
        if (tid == 0) {
            __threadfence();
            atomicAdd(&g_bar, 1u);
            const unsigned target = (unsigned)(t + 1) * NCTA;
            while (*(volatile unsigned*)&g_bar < target) { }
            __threadfence();
        }
        __syncthreads();
    }
}

// ---------------- launch ----------------
extern "C" void kernel_launch(void* const* d_in, const int* in_sizes, int n_in,
                              void* d_out, int out_size) {
    const float* inputs = (const float*)d_in[0];
    const float* W_ih   = (const float*)d_in[1];
    const float* W_hh   = (const float*)d_in[2];
    const float* b_ih   = (const float*)d_in[3];
    const float* b_hh   = (const float*)d_in[4];
    const float* W_out  = (const float*)d_in[5];
    const float* b_out  = (const float*)d_in[6];
    float* out = (float*)d_out;

    void *xg_p = nullptr, *hs_p = nullptr, *bs_p = nullptr;
    cudaGetSymbolAddress(&xg_p, g_xg);
    cudaGetSymbolAddress(&hs_p, g_hs);
    cudaGetSymbolAddress(&bs_p, g_bsum);

    reset_kernel<<<16, 256>>>(b_ih, b_hh);

    // x_gates = inputs @ W_ih^T + (b_ih + b_hh) : [32768, 2048]
    {
        dim3 grid(G4 / 64, (T_STEPS * BATCH) / 64);
        gemm_tn64<<<grid, 256>>>(inputs, W_ih, (const float*)bs_p, (float*)xg_p,
                                 T_STEPS * BATCH, G4, IN_DIM);
    }

    cudaFuncSetAttribute(lstm_recurrent,
                         cudaFuncAttributeMaxDynamicSharedMemorySize, SMEM_BYTES);
    lstm_recurrent<<<NCTA, RTHREADS, SMEM_BYTES>>>(W_hh, out);

    // outputs = hs @ W_out^T + b_out : [32768, 256]
    {
        dim3 grid(OUT_DIM / 64, (T_STEPS * BATCH) / 64);
        gemm_tn64<<<grid, 256>>>((const float*)hs_p, W_out, b_out, out,
                                 T_STEPS * BATCH, OUT_DIM, HID);
    }
}

// round 3
// speedup vs baseline: 1.0084x; 1.0084x over previous
#include <cuda_runtime.h>
#include <cstdint>

#define T_STEPS 512
#define BATCH   64
#define IN_DIM  256
#define HID     512
#define OUT_DIM 256
#define G4      2048
#define NCTA    128

#define SW_STRIDE   516
#define SW_FLOATS   (16 * SW_STRIDE)       // 8256
#define SH_FLOATS   (HID * BATCH)          // 32768
#define SRED_STRIDE 20
#define SRED_FLOATS (192 * SRED_STRIDE)    // 3840
#define RSMEM_BYTES ((SW_FLOATS + SH_FLOATS + SRED_FLOATS) * 4)  // 179456

#define OFF_H ((size_t)T_STEPS * BATCH * OUT_DIM)
#define OFF_C (OFF_H + (size_t)BATCH * HID)

typedef unsigned long long ull;

__device__ float    g_xg[(size_t)T_STEPS * G4 * BATCH];   // [t][g][b]
__device__ float    g_hs[(size_t)T_STEPS * HID * BATCH];  // [t][k][b]
__device__ float    g_bsum[G4];
__device__ unsigned g_bar;

__device__ __forceinline__ ull splat2(float x) {
    ull r; asm("mov.b64 %0, {%1, %1};" : "=l"(r) : "f"(x)); return r;
}
__device__ __forceinline__ void ffma2(ull& d, ull a, ull b) {
    asm("fma.rn.f32x2 %0, %1, %2, %0;" : "+l"(d) : "l"(a), "l"(b));
}
__device__ __forceinline__ float2 unpack2(ull v) {
    float2 r; asm("mov.b64 {%0, %1}, %2;" : "=f"(r.x), "=f"(r.y) : "l"(v)); return r;
}
__device__ __forceinline__ float sigf(float x) { return 1.f / (1.f + __expf(-x)); }
__device__ __forceinline__ void cp_async16(float* dst_smem, const float* src) {
    unsigned d = (unsigned)__cvta_generic_to_shared(dst_smem);
    asm volatile("cp.async.cg.shared.global [%0], [%1], 16;" :: "r"(d), "l"(src) : "memory");
}

__global__ void reset_kernel(const float* __restrict__ b_ih,
                             const float* __restrict__ b_hh) {
    int idx = blockIdx.x * blockDim.x + threadIdx.x;
    if (idx == 0) g_bar = 0u;
    if (idx < G4) g_bsum[idx] = b_ih[idx] + b_hh[idx];
}

// gemm1: g_xg[t][g][b] = sum_i W_ih[g][i]*inp[t][b][i] + bsum[g]
// grid (16, 512): tile 128 g x 64 b, K=256. micro 8m x 4n via FFMA2 m-pairs.
__global__ __launch_bounds__(256) void gemm_xgate(
    const float* __restrict__ inp, const float* __restrict__ W)
{
    __shared__ float As[16][132];
    __shared__ float Bs[16][68];
    const int t  = blockIdx.y;
    const int m0 = blockIdx.x * 128;
    const int tid = threadIdx.x;
    const int tx = tid & 15, ty = tid >> 4;
    const float* B = inp + (size_t)t * BATCH * IN_DIM;

    ull acc[4][4];
    #pragma unroll
    for (int i = 0; i < 4; i++)
        #pragma unroll
        for (int n = 0; n < 4; n++) acc[i][n] = 0ull;

    for (int k0 = 0; k0 < IN_DIM; k0 += 16) {
        #pragma unroll
        for (int u = 0; u < 2; u++) {
            int f4 = u * 256 + tid;
            int rr = f4 >> 2, kq = (f4 & 3) << 2;
            float4 v = *(const float4*)(W + (size_t)(m0 + rr) * IN_DIM + k0 + kq);
            As[kq + 0][rr] = v.x; As[kq + 1][rr] = v.y;
            As[kq + 2][rr] = v.z; As[kq + 3][rr] = v.w;
        }
        {
            int rr = tid >> 2, kq = (tid & 3) << 2;
            float4 v = *(const float4*)(B + (size_t)rr * IN_DIM + k0 + kq);
            Bs[kq + 0][rr] = v.x; Bs[kq + 1][rr] = v.y;
            Bs[kq + 2][rr] = v.z; Bs[kq + 3][rr] = v.w;
        }
        __syncthreads();
        #pragma unroll
        for (int kk = 0; kk < 16; kk++) {
            ulonglong2 a01 = *(const ulonglong2*)&As[kk][ty * 8];
            ulonglong2 a23 = *(const ulonglong2*)&As[kk][ty * 8 + 4];
            float4 bv = *(const float4*)&Bs[kk][tx * 4];
            ull bs0 = splat2(bv.x), bs1 = splat2(bv.y);
            ull bs2 = splat2(bv.z), bs3 = splat2(bv.w);
            ffma2(acc[0][0], a01.x, bs0); ffma2(acc[1][0], a01.y, bs0);
            ffma2(acc[2][0], a23.x, bs0); ffma2(acc[3][0], a23.y, bs0);
            ffma2(acc[0][1], a01.x, bs1); ffma2(acc[1][1], a01.y, bs1);
            ffma2(acc[2][1], a23.x, bs1); ffma2(acc[3][1], a23.y, bs1);
            ffma2(acc[0][2], a01.x, bs2); ffma2(acc[1][2], a01.y, bs2);
            ffma2(acc[2][2], a23.x, bs2); ffma2(acc[3][2], a23.y, bs2);
            ffma2(acc[0][3], a01.x, bs3); ffma2(acc[1][3], a01.y, bs3);
            ffma2(acc[2][3], a23.x, bs3); ffma2(acc[3][3], a23.y, bs3);
        }
        __syncthreads();
    }

    float* C = g_xg + ((size_t)t * G4 + m0) * BATCH;
    #pragma unroll
    for (int mp = 0; mp < 4; mp++) {
        float2 u0 = unpack2(acc[mp][0]);
        float2 u1 = unpack2(acc[mp][1]);
        float2 u2 = unpack2(acc[mp][2]);
        float2 u3 = unpack2(acc[mp][3]);
        int mA = ty * 8 + mp * 2, mB = mA + 1;
        float bA = g_bsum[m0 + mA], bB = g_bsum[m0 + mB];
        *(float4*)(C + (size_t)mA * BATCH + tx * 4) =
            make_float4(u0.x + bA, u1.x + bA, u2.x + bA, u3.x + bA);
        *(float4*)(C + (size_t)mB * BATCH + tx * 4) =
            make_float4(u0.y + bB, u1.y + bB, u2.y + bB, u3.y + bB);
    }
}

// gemm2: out[t][b][o] = sum_k g_hs[t][k][b]*W_out[o][k] + b_out[o]
// grid (4, 512): tile 64 b x 64 o, K=512. micro 4m x 4n via FFMA2 m-pairs.
__global__ __launch_bounds__(256) void gemm_out(
    const float* __restrict__ Wout, const float* __restrict__ bout,
    float* __restrict__ out)
{
    __shared__ float As[16][68];
    __shared__ float Bs[16][68];
    const int t  = blockIdx.y;
    const int n0 = blockIdx.x * 64;
    const int tid = threadIdx.x;
    const int tx = tid & 15, ty = tid >> 4;
    const float* A = g_hs + (size_t)t * HID * BATCH;

    ull acc[2][4];
    #pragma unroll
    for (int i = 0; i < 2; i++)
        #pragma unroll
        for (int n = 0; n < 4; n++) acc[i][n] = 0ull;

    for (int k0 = 0; k0 < HID; k0 += 16) {
        {
            int kk = tid >> 4, c4 = (tid & 15) * 4;
            *(float4*)&As[kk][c4] = *(const float4*)(A + (size_t)(k0 + kk) * BATCH + c4);
        }
        {
            int rr = tid >> 2, kq = (tid & 3) << 2;
            float4 v = *(const float4*)(Wout + (size_t)(n0 + rr) * HID + k0 + kq);
            Bs[kq + 0][rr] = v.x; Bs[kq + 1][rr] = v.y;
            Bs[kq + 2][rr] = v.z; Bs[kq + 3][rr] = v.w;
        }
        __syncthreads();
        #pragma unroll
        for (int kk = 0; kk < 16; kk++) {
            ulonglong2 a = *(const ulonglong2*)&As[kk][ty * 4];
            float4 bv = *(const float4*)&Bs[kk][tx * 4];
            ull bs0 = splat2(bv.x), bs1 = splat2(bv.y);
            ull bs2 = splat2(bv.z), bs3 = splat2(bv.w);
            ffma2(acc[0][0], a.x, bs0); ffma2(acc[1][0], a.y, bs0);
            ffma2(acc[0][1], a.x, bs1); ffma2(acc[1][1], a.y, bs1);
            ffma2(acc[0][2], a.x, bs2); ffma2(acc[1][2], a.y, bs2);
            ffma2(acc[0][3], a.x, bs3); ffma2(acc[1][3], a.y, bs3);
        }
        __syncthreads();
    }

    float4 bb = *(const float4*)(bout + n0 + tx * 4);
    #pragma unroll
    for (int mp = 0; mp < 2; mp++) {
        float2 u0 = unpack2(acc[mp][0]);
        float2 u1 = unpack2(acc[mp][1]);
        float2 u2 = unpack2(acc[mp][2]);
        float2 u3 = unpack2(acc[mp][3]);
        int mA = ty * 4 + mp * 2, mB = mA + 1;
        *(float4*)(out + ((size_t)t * BATCH + mA) * OUT_DIM + n0 + tx * 4) =
            make_float4(u0.x + bb.x, u1.x + bb.y, u2.x + bb.z, u3.x + bb.w);
        *(float4*)(out + ((size_t)t * BATCH + mB) * OUT_DIM + n0 + tx * 4) =
            make_float4(u0.y + bb.x, u1.y + bb.y, u2.y + bb.z, u3.y + bb.w);
    }
}

// persistent recurrent kernel: 128 CTAs x 256 threads = 4 K-slices x 64.
// thread: column j = j0 + (s>>4), batches bg..bg+3, all 4 gates, FFMA2-packed.
__global__ void __launch_bounds__(256, 1)
lstm_recurrent(const float* __restrict__ W_hh, float* __restrict__ out)
{
    extern __shared__ float smem[];
    float* sW   = smem;                 // 16 rows x 516
    float* sH   = smem + SW_FLOATS;     // [512 k][64 b]
    float* sRed = sH + SH_FLOATS;       // 192 x 20

    const int tid = threadIdx.x;
    const int j0  = blockIdx.x << 2;
    const int hk  = tid >> 6;
    const int s   = tid & 63;
    const int ii  = s >> 4;
    const int bg  = (s & 15) << 2;
    const int j   = j0 + ii;

    #pragma unroll
    for (int u = 0; u < 8; u++) {
        int f4 = u * 256 + tid;
        int rr = f4 >> 7;
        int kk = (f4 & 127) << 2;
        int q = rr >> 2, iw = rr & 3;
        float4 v = *(const float4*)(W_hh + (size_t)(q * HID + j0 + iw) * HID + kk);
        *(float4*)(sW + rr * SW_STRIDE + kk) = v;
    }
    __syncthreads();

    float cst[4] = {0.f, 0.f, 0.f, 0.f};

    for (int t = 0; t < T_STEPS; t++) {
        float xg[4][4];
        if (hk == 0) {
            #pragma unroll
            for (int q = 0; q < 4; q++) {
                float4 v = *(const float4*)(g_xg + ((size_t)t * G4 + q * HID + j) * BATCH + bg);
                xg[q][0] = v.x; xg[q][1] = v.y; xg[q][2] = v.z; xg[q][3] = v.w;
            }
        }

        ull acc[4][2];
        #pragma unroll
        for (int q = 0; q < 4; q++) { acc[q][0] = 0ull; acc[q][1] = 0ull; }

        if (t > 0) {
            const float* hsrc = g_hs + ((size_t)(t - 1) * HID + hk * 128) * BATCH;
            float* dst = sH + hk * 128 * BATCH;
            #pragma unroll
            for (int u = 0; u < 16; u++) {
                int f4 = u * 64 + s;
                cp_async16(dst + f4 * 4, hsrc + f4 * 4);
            }
            asm volatile("cp.async.commit_group;" ::: "memory");
            #pragma unroll
            for (int u = 16; u < 32; u++) {
                int f4 = u * 64 + s;
                cp_async16(dst + f4 * 4, hsrc + f4 * 4);
            }
            asm volatile("cp.async.commit_group;" ::: "memory");
            asm volatile("cp.async.wait_group 1;" ::: "memory");
            asm volatile("bar.sync %0, 64;" :: "r"(1 + hk) : "memory");

            const float* hbase = sH + hk * 128 * BATCH + bg;
            const float* wbase = sW + ii * SW_STRIDE + hk * 128;

            #pragma unroll
            for (int half = 0; half < 2; half++) {
                if (half == 1) {
                    asm volatile("cp.async.wait_group 0;" ::: "memory");
                    asm volatile("bar.sync %0, 64;" :: "r"(1 + hk) : "memory");
                }
                #pragma unroll 4
                for (int kl = half * 64; kl < half * 64 + 64; kl += 4) {
                    ulonglong2 h0 = *(const ulonglong2*)(hbase + (size_t)(kl + 0) * BATCH);
                    ulonglong2 h1 = *(const ulonglong2*)(hbase + (size_t)(kl + 1) * BATCH);
                    ulonglong2 h2 = *(const ulonglong2*)(hbase + (size_t)(kl + 2) * BATCH);
                    ulonglong2 h3 = *(const ulonglong2*)(hbase + (size_t)(kl + 3) * BATCH);
                    #pragma unroll
                    for (int q = 0; q < 4; q++) {
                        float4 wv = *(const float4*)(wbase + q * 4 * SW_STRIDE + kl);
                        ull w;
                        w = splat2(wv.x); ffma2(acc[q][0], h0.x, w); ffma2(acc[q][1], h0.y, w);
                        w = splat2(wv.y); ffma2(acc[q][0], h1.x, w); ffma2(acc[q][1], h1.y, w);
                        w = splat2(wv.z); ffma2(acc[q][0], h2.x, w); ffma2(acc[q][1], h2.y, w);
                        w = splat2(wv.w); ffma2(acc[q][0], h3.x, w); ffma2(acc[q][1], h3.y, w);
                    }
                }
            }
        }

        if (hk != 0) {
            float* p = sRed + ((hk - 1) * 64 + s) * SRED_STRIDE;
            #pragma unroll
            for (int q = 0; q < 4; q++) {
                float2 lo = unpack2(acc[q][0]);
                float2 hi = unpack2(acc[q][1]);
                *(float4*)(p + q * 4) = make_float4(lo.x, lo.y, hi.x, hi.y);
            }
        }
        __syncthreads();

        if (hk == 0) {
            float a[4][4];
            #pragma unroll
            for (int q = 0; q < 4; q++) {
                float2 lo = unpack2(acc[q][0]);
                float2 hi = unpack2(acc[q][1]);
                a[q][0] = lo.x + xg[q][0]; a[q][1] = lo.y + xg[q][1];
                a[q][2] = hi.x + xg[q][2]; a[q][3] = hi.y + xg[q][3];
            }
            #pragma unroll
            for (int sl = 0; sl < 3; sl++) {
                const float* p = sRed + (sl * 64 + s) * SRED_STRIDE;
                #pragma unroll
                for (int q = 0; q < 4; q++) {
                    float4 v = *(const float4*)(p + q * 4);
                    a[q][0] += v.x; a[q][1] += v.y; a[q][2] += v.z; a[q][3] += v.w;
                }
            }
            float hnew[4];
            #pragma unroll
            for (int b = 0; b < 4; b++) {
                float iv = sigf(a[0][b]);
                float fv = sigf(a[1][b]);
                float gv = tanhf(a[2][b]);
                float ov = sigf(a[3][b]);
                cst[b] = fv * cst[b] + iv * gv;
                hnew[b] = ov * tanhf(cst[b]);
            }
            *(float4*)(g_hs + ((size_t)t * HID + j) * BATCH + bg) =
                make_float4(hnew[0], hnew[1], hnew[2], hnew[3]);
            if (t == T_STEPS - 1) {
                #pragma unroll
                for (int b = 0; b < 4; b++) {
                    out[OFF_H + (size_t)(bg + b) * HID + j] = hnew[b];
                    out[OFF_C + (size_t)(bg + b) * HID + j] = cst[b];
                }
            }
        }
        __syncthreads();

        if (tid == 0) {
            __threadfence();
            atomicAdd(&g_bar, 1u);
            const unsigned target = (unsigned)(t + 1) * NCTA;
            while (*(volatile unsigned*)&g_bar < target) { }
            __threadfence();
        }
        __syncthreads();
    }
}

extern "C" void kernel_launch(void* const* d_in, const int* in_sizes, int n_in,
                              void* d_out, int out_size) {
    const float* inputs = (const float*)d_in[0];
    const float* W_ih   = (const float*)d_in[1];
    const float* W_hh   = (const float*)d_in[2];
    const float* b_ih   = (const float*)d_in[3];
    const float* b_hh   = (const float*)d_in[4];
    const float* W_out  = (const float*)d_in[5];
    const float* b_out  = (const float*)d_in[6];
    float* out = (float*)d_out;

    reset_kernel<<<16, 256>>>(b_ih, b_hh);

    gemm_xgate<<<dim3(G4 / 128, T_STEPS), 256>>>(inputs, W_ih);

    cudaFuncSetAttribute(lstm_recurrent,
                         cudaFuncAttributeMaxDynamicSharedMemorySize, RSMEM_BYTES);
    lstm_recurrent<<<NCTA, 256, RSMEM_BYTES>>>(W_hh, out);

    gemm_out<<<dim3(OUT_DIM / 64, T_STEPS), 256>>>(W_out, b_out, out);
}

// round 4
// speedup vs baseline: 1.0494x; 1.0407x over previous
#include <cuda_runtime.h>
#include <cstdint>

#define T_STEPS 512
#define BATCH   64
#define IN_DIM  256
#define HID     512
#define OUT_DIM 256
#define G4      2048
#define NCTA    128

#define SW2_STRIDE  1032                     // 1024 splatted + 8 pad (16B aligned)
#define SW2_FLOATS  (16 * SW2_STRIDE)        // 16512
#define SRED_STRIDE 20
#define SRED_FLOATS (192 * SRED_STRIDE)      // 3840
#define RSMEM_BYTES ((SW2_FLOATS + SRED_FLOATS) * 4)   // 81408

#define OFF_H ((size_t)T_STEPS * BATCH * OUT_DIM)
#define OFF_C (OFF_H + (size_t)BATCH * HID)

typedef unsigned long long ull;

__device__ float    g_xg[(size_t)T_STEPS * G4 * BATCH];   // [t][g][b]
__device__ float    g_hs[(size_t)T_STEPS * HID * BATCH];  // [t][k][b]
__device__ float    g_bsum[G4];
__device__ unsigned g_bar;

__device__ __forceinline__ void ffma2(ull& d, ull a, ull b) {
    asm("fma.rn.f32x2 %0, %1, %2, %0;" : "+l"(d) : "l"(a), "l"(b));
}
__device__ __forceinline__ float2 unpack2(ull v) {
    float2 r; asm("mov.b64 {%0, %1}, %2;" : "=f"(r.x), "=f"(r.y) : "l"(v)); return r;
}
__device__ __forceinline__ float sigf(float x) {
    return __fdividef(1.f, 1.f + __expf(-x));
}
__device__ __forceinline__ float tanhfast(float x) {
    float e = __expf(-2.f * fabsf(x));           // in (0,1], no overflow
    float r = __fdividef(1.f - e, 1.f + e);
    return copysignf(r, x);
}

__global__ void reset_kernel(const float* __restrict__ b_ih,
                             const float* __restrict__ b_hh) {
    int idx = blockIdx.x * blockDim.x + threadIdx.x;
    if (idx == 0) g_bar = 0u;
    if (idx < G4) g_bsum[idx] = b_ih[idx] + b_hh[idx];
}

// ---------- gemm1: g_xg[t][g][b] = sum_i W_ih[g][i]*inp[t][b][i] + bsum[g]
// grid (16, 512): tile 128 g x 64 b, K=256. micro 8m x 4n. B pre-splatted.
__global__ __launch_bounds__(256) void gemm_xgate(
    const float* __restrict__ inp, const float* __restrict__ W)
{
    __shared__ float As[16][132];    // [k][m], m = gate within tile
    __shared__ float Bs[16][136];    // [k][2b splatted]
    const int t  = blockIdx.y;
    const int m0 = blockIdx.x * 128;
    const int tid = threadIdx.x;
    const int tx = tid & 15, ty = tid >> 4;
    const float* B = inp + (size_t)t * BATCH * IN_DIM;

    ull acc[4][4];
    #pragma unroll
    for (int i = 0; i < 4; i++)
        #pragma unroll
        for (int n = 0; n < 4; n++) acc[i][n] = 0ull;

    for (int k0 = 0; k0 < IN_DIM; k0 += 16) {
        #pragma unroll
        for (int u = 0; u < 2; u++) {
            int f4 = u * 256 + tid;
            int rr = f4 >> 2, kq = (f4 & 3) << 2;
            float4 v = *(const float4*)(W + (size_t)(m0 + rr) * IN_DIM + k0 + kq);
            As[kq + 0][rr] = v.x; As[kq + 1][rr] = v.y;
            As[kq + 2][rr] = v.z; As[kq + 3][rr] = v.w;
        }
        {
            int rr = tid >> 2, kq = (tid & 3) << 2;    // rr = batch 0..63
            float4 v = *(const float4*)(B + (size_t)rr * IN_DIM + k0 + kq);
            *(float2*)&Bs[kq + 0][2 * rr] = make_float2(v.x, v.x);
            *(float2*)&Bs[kq + 1][2 * rr] = make_float2(v.y, v.y);
            *(float2*)&Bs[kq + 2][2 * rr] = make_float2(v.z, v.z);
            *(float2*)&Bs[kq + 3][2 * rr] = make_float2(v.w, v.w);
        }
        __syncthreads();
        #pragma unroll
        for (int kk = 0; kk < 16; kk++) {
            ulonglong2 a01 = *(const ulonglong2*)&As[kk][ty * 8];
            ulonglong2 a23 = *(const ulonglong2*)&As[kk][ty * 8 + 4];
            ulonglong2 b01 = *(const ulonglong2*)&Bs[kk][tx * 8];
            ulonglong2 b23 = *(const ulonglong2*)&Bs[kk][tx * 8 + 4];
            ffma2(acc[0][0], a01.x, b01.x); ffma2(acc[1][0], a01.y, b01.x);
            ffma2(acc[2][0], a23.x, b01.x); ffma2(acc[3][0], a23.y, b01.x);
            ffma2(acc[0][1], a01.x, b01.y); ffma2(acc[1][1], a01.y, b01.y);
            ffma2(acc[2][1], a23.x, b01.y); ffma2(acc[3][1], a23.y, b01.y);
            ffma2(acc[0][2], a01.x, b23.x); ffma2(acc[1][2], a01.y, b23.x);
            ffma2(acc[2][2], a23.x, b23.x); ffma2(acc[3][2], a23.y, b23.x);
            ffma2(acc[0][3], a01.x, b23.y); ffma2(acc[1][3], a01.y, b23.y);
            ffma2(acc[2][3], a23.x, b23.y); ffma2(acc[3][3], a23.y, b23.y);
        }
        __syncthreads();
    }

    float* C = g_xg + ((size_t)t * G4 + m0) * BATCH;
    #pragma unroll
    for (int mp = 0; mp < 4; mp++) {
        float2 u0 = unpack2(acc[mp][0]);
        float2 u1 = unpack2(acc[mp][1]);
        float2 u2 = unpack2(acc[mp][2]);
        float2 u3 = unpack2(acc[mp][3]);
        int mA = ty * 8 + mp * 2, mB = mA + 1;
        float bA = g_bsum[m0 + mA], bB = g_bsum[m0 + mB];
        *(float4*)(C + (size_t)mA * BATCH + tx * 4) =
            make_float4(u0.x + bA, u1.x + bA, u2.x + bA, u3.x + bA);
        *(float4*)(C + (size_t)mB * BATCH + tx * 4) =
            make_float4(u0.y + bB, u1.y + bB, u2.y + bB, u3.y + bB);
    }
}

// ---------- gemm2: out[t][b][o] = sum_k g_hs[t][k][b]*W_out[o][k] + b_out[o]
// grid (4, 512): tile 64 b x 64 o, K=512. micro 4m x 4n. W pre-splatted.
__global__ __launch_bounds__(256) void gemm_out(
    const float* __restrict__ Wout, const float* __restrict__ bout,
    float* __restrict__ out)
{
    __shared__ float As[16][68];     // [k][b] direct copy
    __shared__ float Bs[16][136];    // [k][2o splatted]
    const int t  = blockIdx.y;
    const int n0 = blockIdx.x * 64;
    const int tid = threadIdx.x;
    const int tx = tid & 15, ty = tid >> 4;
    const float* A = g_hs + (size_t)t * HID * BATCH;

    ull acc[2][4];
    #pragma unroll
    for (int i = 0; i < 2; i++)
        #pragma unroll
        for (int n = 0; n < 4; n++) acc[i][n] = 0ull;

    for (int k0 = 0; k0 < HID; k0 += 16) {
        {
            int kk = tid >> 4, c4 = (tid & 15) * 4;
            *(float4*)&As[kk][c4] = *(const float4*)(A + (size_t)(k0 + kk) * BATCH + c4);
        }
        {
            int rr = tid >> 2, kq = (tid & 3) << 2;    // rr = o 0..63
            float4 v = *(const float4*)(Wout + (size_t)(n0 + rr) * HID + k0 + kq);
            *(float2*)&Bs[kq + 0][2 * rr] = make_float2(v.x, v.x);
            *(float2*)&Bs[kq + 1][2 * rr] = make_float2(v.y, v.y);
            *(float2*)&Bs[kq + 2][2 * rr] = make_float2(v.z, v.z);
            *(float2*)&Bs[kq + 3][2 * rr] = make_float2(v.w, v.w);
        }
        __syncthreads();
        #pragma unroll
        for (int kk = 0; kk < 16; kk++) {
            ulonglong2 a  = *(const ulonglong2*)&As[kk][ty * 4];
            ulonglong2 b01 = *(const ulonglong2*)&Bs[kk][tx * 8];
            ulonglong2 b23 = *(const ulonglong2*)&Bs[kk][tx * 8 + 4];
            ffma2(acc[0][0], a.x, b01.x); ffma2(acc[1][0], a.y, b01.x);
            ffma2(acc[0][1], a.x, b01.y); ffma2(acc[1][1], a.y, b01.y);
            ffma2(acc[0][2], a.x, b23.x); ffma2(acc[1][2], a.y, b23.x);
            ffma2(acc[0][3], a.x, b23.y); ffma2(acc[1][3], a.y, b23.y);
        }
        __syncthreads();
    }

    float4 bb = *(const float4*)(bout + n0 + tx * 4);
    #pragma unroll
    for (int mp = 0; mp < 2; mp++) {
        float2 u0 = unpack2(acc[mp][0]);
        float2 u1 = unpack2(acc[mp][1]);
        float2 u2 = unpack2(acc[mp][2]);
        float2 u3 = unpack2(acc[mp][3]);
        int mA = ty * 4 + mp * 2, mB = mA + 1;
        *(float4*)(out + ((size_t)t * BATCH + mA) * OUT_DIM + n0 + tx * 4) =
            make_float4(u0.x + bb.x, u1.x + bb.y, u2.x + bb.z, u3.x + bb.w);
        *(float4*)(out + ((size_t)t * BATCH + mB) * OUT_DIM + n0 + tx * 4) =
            make_float4(u0.y + bb.x, u1.y + bb.y, u2.y + bb.z, u3.y + bb.w);
    }
}

// ---------- persistent recurrent kernel ----------
// 128 CTAs x 256 threads = 4 K-slices x (4 cols x 16 batch-quads).
// W_hh pre-splatted in smem; h read straight from L2 via __ldg.
__global__ void __launch_bounds__(256, 1)
lstm_recurrent(const float* __restrict__ W_hh, float* __restrict__ out)
{
    extern __shared__ float smem[];
    float* sW2  = smem;                 // 16 rows x 1032 (splatted)
    float* sRed = smem + SW2_FLOATS;    // 192 x 20

    const int tid = threadIdx.x;
    const int j0  = blockIdx.x << 2;
    const int hk  = tid >> 6;           // K-slice: k in [128*hk, 128*hk+128)
    const int s   = tid & 63;
    const int ii  = s >> 4;             // column within CTA
    const int bg  = (s & 15) << 2;      // batches bg..bg+3
    const int j   = j0 + ii;

    // stage W_hh pre-splatted: row r = q*4+iw holds W[q*512+j0+iw][k] duplicated
    #pragma unroll
    for (int u = 0; u < 8; u++) {
        int f4 = u * 256 + tid;
        int rr = f4 >> 7;
        int kk = (f4 & 127) << 2;
        int q = rr >> 2, iw = rr & 3;
        float4 v = *(const float4*)(W_hh + (size_t)(q * HID + j0 + iw) * HID + kk);
        float* d = sW2 + rr * SW2_STRIDE + 2 * kk;
        *(float4*)(d    ) = make_float4(v.x, v.x, v.y, v.y);
        *(float4*)(d + 4) = make_float4(v.z, v.z, v.w, v.w);
    }
    __syncthreads();

    float cst[4] = {0.f, 0.f, 0.f, 0.f};
    const float* wb0 = sW2 + ii * SW2_STRIDE + hk * 256;   // q=0 row, this slice

    for (int t = 0; t < T_STEPS; t++) {
        float xg[4][4];
        if (hk == 0) {
            #pragma unroll
            for (int q = 0; q < 4; q++) {
                float4 v = *(const float4*)(g_xg + ((size_t)t * G4 + q * HID + j) * BATCH + bg);
                xg[q][0] = v.x; xg[q][1] = v.y; xg[q][2] = v.z; xg[q][3] = v.w;
            }
        }

        ull acc[4][2];
        #pragma unroll
        for (int q = 0; q < 4; q++) { acc[q][0] = 0ull; acc[q][1] = 0ull; }

        if (t > 0) {
            const float* hsrc = g_hs + ((size_t)(t - 1) * HID + hk * 128) * BATCH + bg;
            #pragma unroll 4
            for (int kl = 0; kl < 128; kl += 4) {
                ulonglong2 h0 = __ldg((const ulonglong2*)(hsrc + (size_t)(kl + 0) * BATCH));
                ulonglong2 h1 = __ldg((const ulonglong2*)(hsrc + (size_t)(kl + 1) * BATCH));
                ulonglong2 h2 = __ldg((const ulonglong2*)(hsrc + (size_t)(kl + 2) * BATCH));
                ulonglong2 h3 = __ldg((const ulonglong2*)(hsrc + (size_t)(kl + 3) * BATCH));
                #pragma unroll
                for (int q = 0; q < 4; q++) {
                    const float* wr = wb0 + q * 4 * SW2_STRIDE + 2 * kl;
                    ulonglong2 w01 = *(const ulonglong2*)(wr);
                    ulonglong2 w23 = *(const ulonglong2*)(wr + 4);
                    ffma2(acc[q][0], h0.x, w01.x); ffma2(acc[q][1], h0.y, w01.x);
                    ffma2(acc[q][0], h1.x, w01.y); ffma2(acc[q][1], h1.y, w01.y);
                    ffma2(acc[q][0], h2.x, w23.x); ffma2(acc[q][1], h2.y, w23.x);
                    ffma2(acc[q][0], h3.x, w23.y); ffma2(acc[q][1], h3.y, w23.y);
                }
            }
        }

        if (hk != 0) {
            float* p = sRed + ((hk - 1) * 64 + s) * SRED_STRIDE;
            #pragma unroll
            for (int q = 0; q < 4; q++) {
                float2 lo = unpack2(acc[q][0]);
                float2 hi = unpack2(acc[q][1]);
                *(float4*)(p + q * 4) = make_float4(lo.x, lo.y, hi.x, hi.y);
            }
        }
        __syncthreads();

        if (hk == 0) {
            float a[4][4];
            #pragma unroll
            for (int q = 0; q < 4; q++) {
                float2 lo = unpack2(acc[q][0]);
                float2 hi = unpack2(acc[q][1]);
                a[q][0] = lo.x + xg[q][0]; a[q][1] = lo.y + xg[q][1];
                a[q][2] = hi.x + xg[q][2]; a[q][3] = hi.y + xg[q][3];
            }
            #pragma unroll
            for (int sl = 0; sl < 3; sl++) {
                const float* p = sRed + (sl * 64 + s) * SRED_STRIDE;
                #pragma unroll
                for (int q = 0; q < 4; q++) {
                    float4 v = *(const float4*)(p + q * 4);
                    a[q][0] += v.x; a[q][1] += v.y; a[q][2] += v.z; a[q][3] += v.w;
                }
            }
            float hnew[4];
            #pragma unroll
            for (int b = 0; b < 4; b++) {
                float iv = sigf(a[0][b]);
                float fv = sigf(a[1][b]);
                float gv = tanhfast(a[2][b]);
                float ov = sigf(a[3][b]);
                cst[b] = fv * cst[b] + iv * gv;
                hnew[b] = ov * tanhfast(cst[b]);
            }
            *(float4*)(g_hs + ((size_t)t * HID + j) * BATCH + bg) =
                make_float4(hnew[0], hnew[1], hnew[2], hnew[3]);
            if (t == T_STEPS - 1) {
                #pragma unroll
                for (int b = 0; b < 4; b++) {
                    out[OFF_H + (size_t)(bg + b) * HID + j] = hnew[b];
                    out[OFF_C + (size_t)(bg + b) * HID + j] = cst[b];
                }
            }
        }
        __syncthreads();

        if (tid == 0) {
            __threadfence();
            atomicAdd(&g_bar, 1u);
            const unsigned target = (unsigned)(t + 1) * NCTA;
            while (*(volatile unsigned*)&g_bar < target) { }
            __threadfence();
        }
        __syncthreads();
    }
}

extern "C" void kernel_launch(void* const* d_in, const int* in_sizes, int n_in,
                              void* d_out, int out_size) {
    const float* inputs = (const float*)d_in[0];
    const float* W_ih   = (const float*)d_in[1];
    const float* W_hh   = (const float*)d_in[2];
    const float* b_ih   = (const float*)d_in[3];
    const float* b_hh   = (const float*)d_in[4];
    const float* W_out  = (const float*)d_in[5];
    const float* b_out  = (const float*)d_in[6];
    float* out = (float*)d_out;

    reset_kernel<<<16, 256>>>(b_ih, b_hh);

    gemm_xgate<<<dim3(G4 / 128, T_STEPS), 256>>>(inputs, W_ih);

    cudaFuncSetAttribute(lstm_recurrent,
                         cudaFuncAttributeMaxDynamicSharedMemorySize, RSMEM_BYTES);
    lstm_recurrent<<<NCTA, 256, RSMEM_BYTES>>>(W_hh, out);

    gemm_out<<<dim3(OUT_DIM / 64, T_STEPS), 256>>>(W_out, b_out, out);
}

// round 5
// speedup vs baseline: 1.2160x; 1.1588x over previous
#include <cuda_runtime.h>
#include <cstdint>

#define T_STEPS 512
#define BATCH   64
#define IN_DIM  256
#define HID     512
#define OUT_DIM 256
#define G4      2048
#define NCTA    128

#define SW2_STRIDE  1032                     // 1024 splatted + 8 pad
#define SW2_FLOATS  (16 * SW2_STRIDE)        // 16512
#define SRED_SLICE  (64 * 68)                // 4352 floats per slice
#define SRED_FLOATS (4 * SRED_SLICE)         // 17408
#define RSMEM_BYTES ((SW2_FLOATS + SRED_FLOATS) * 4)   // 135680

#define OFF_H ((size_t)T_STEPS * BATCH * OUT_DIM)
#define OFF_C (OFF_H + (size_t)BATCH * HID)

typedef unsigned long long ull;

__device__ float    g_xg[(size_t)T_STEPS * G4 * BATCH];   // [t][g][b]
__device__ float    g_hs[(size_t)T_STEPS * HID * BATCH];  // [t][k][b]
__device__ float    g_bsum[G4];
__device__ unsigned g_bar;

__device__ __forceinline__ void ffma2(ull& d, ull a, ull b) {
    asm("fma.rn.f32x2 %0, %1, %2, %0;" : "+l"(d) : "l"(a), "l"(b));
}
__device__ __forceinline__ float2 unpack2(ull v) {
    float2 r; asm("mov.b64 {%0, %1}, %2;" : "=f"(r.x), "=f"(r.y) : "l"(v)); return r;
}
__device__ __forceinline__ float sigf(float x) {
    return __fdividef(1.f, 1.f + __expf(-x));
}
__device__ __forceinline__ float tanhfast(float x) {
    float e = __expf(-2.f * fabsf(x));
    float r = __fdividef(1.f - e, 1.f + e);
    return copysignf(r, x);
}

__global__ void reset_kernel(const float* __restrict__ b_ih,
                             const float* __restrict__ b_hh) {
    int idx = blockIdx.x * blockDim.x + threadIdx.x;
    if (idx == 0) g_bar = 0u;
    if (idx < G4) g_bsum[idx] = b_ih[idx] + b_hh[idx];
}

// ================= gemm1: g_xg[t][g][b] = sum_i W_ih[g][i]*inp[t][b][i] + bsum
// grid (16, 512): tile 128 g x 64 b, BK=16. FFMA2, conflict-free splat B.
__global__ __launch_bounds__(256) void gemm_xgate(
    const float* __restrict__ inp, const float* __restrict__ W)
{
    __shared__ float As[16][132];      // [k][gate]
    __shared__ float Bsw[16 * 196];    // [k][16 blocks x 12 floats (4 splat pairs + pad)]
    const int t  = blockIdx.y;
    const int m0 = blockIdx.x * 128;
    const int tid = threadIdx.x;
    const int tx = tid & 15, ty = tid >> 4;
    const float* B = inp + (size_t)t * BATCH * IN_DIM;

    ull acc[4][4];
    #pragma unroll
    for (int i = 0; i < 4; i++)
        #pragma unroll
        for (int n = 0; n < 4; n++) acc[i][n] = 0ull;

    const int rr = tid >> 2;            // staging row / batch
    const int kq = (tid & 3) << 2;
    const int bbase = (rr >> 2) * 12 + (rr & 3) * 2;

    for (int k0 = 0; k0 < IN_DIM; k0 += 16) {
        #pragma unroll
        for (int u = 0; u < 2; u++) {
            int f4 = u * 256 + tid;
            int r2 = f4 >> 2, k2 = (f4 & 3) << 2;
            float4 v = *(const float4*)(W + (size_t)(m0 + r2) * IN_DIM + k0 + k2);
            As[k2 + 0][r2] = v.x; As[k2 + 1][r2] = v.y;
            As[k2 + 2][r2] = v.z; As[k2 + 3][r2] = v.w;
        }
        {
            float4 v = *(const float4*)(B + (size_t)rr * IN_DIM + k0 + kq);
            *(float2*)&Bsw[(kq + 0) * 196 + bbase] = make_float2(v.x, v.x);
            *(float2*)&Bsw[(kq + 1) * 196 + bbase] = make_float2(v.y, v.y);
            *(float2*)&Bsw[(kq + 2) * 196 + bbase] = make_float2(v.z, v.z);
            *(float2*)&Bsw[(kq + 3) * 196 + bbase] = make_float2(v.w, v.w);
        }
        __syncthreads();
        #pragma unroll
        for (int kk = 0; kk < 16; kk++) {
            ulonglong2 a01 = *(const ulonglong2*)&As[kk][ty * 8];
            ulonglong2 a23 = *(const ulonglong2*)&As[kk][ty * 8 + 4];
            const float* bp = Bsw + kk * 196 + tx * 12;
            ulonglong2 b01 = *(const ulonglong2*)bp;
            ulonglong2 b23 = *(const ulonglong2*)(bp + 4);
            ffma2(acc[0][0], a01.x, b01.x); ffma2(acc[1][0], a01.y, b01.x);
            ffma2(acc[2][0], a23.x, b01.x); ffma2(acc[3][0], a23.y, b01.x);
            ffma2(acc[0][1], a01.x, b01.y); ffma2(acc[1][1], a01.y, b01.y);
            ffma2(acc[2][1], a23.x, b01.y); ffma2(acc[3][1], a23.y, b01.y);
            ffma2(acc[0][2], a01.x, b23.x); ffma2(acc[1][2], a01.y, b23.x);
            ffma2(acc[2][2], a23.x, b23.x); ffma2(acc[3][2], a23.y, b23.x);
            ffma2(acc[0][3], a01.x, b23.y); ffma2(acc[1][3], a01.y, b23.y);
            ffma2(acc[2][3], a23.x, b23.y); ffma2(acc[3][3], a23.y, b23.y);
        }
        __syncthreads();
    }

    float* C = g_xg + ((size_t)t * G4 + m0) * BATCH;
    #pragma unroll
    for (int mp = 0; mp < 4; mp++) {
        float2 u0 = unpack2(acc[mp][0]);
        float2 u1 = unpack2(acc[mp][1]);
        float2 u2 = unpack2(acc[mp][2]);
        float2 u3 = unpack2(acc[mp][3]);
        int mA = ty * 8 + mp * 2, mB = mA + 1;
        float bA = g_bsum[m0 + mA], bB = g_bsum[m0 + mB];
        *(float4*)(C + (size_t)mA * BATCH + tx * 4) =
            make_float4(u0.x + bA, u1.x + bA, u2.x + bA, u3.x + bA);
        *(float4*)(C + (size_t)mB * BATCH + tx * 4) =
            make_float4(u0.y + bB, u1.y + bB, u2.y + bB, u3.y + bB);
    }
}

// ================= gemm2: out[t][b][o] = sum_k g_hs[t][k][b]*W_out[o][k] + b_out
// grid (4, 512): tile 64 b x 64 o, BK=16. FFMA2 over b-pairs, splat W swizzled.
__global__ __launch_bounds__(256) void gemm_out(
    const float* __restrict__ Wout, const float* __restrict__ bout,
    float* __restrict__ out)
{
    __shared__ float As2[16][68];      // [k][b] direct copy
    __shared__ float Wsw[16 * 196];    // splat W, conflict-free blocks
    const int t  = blockIdx.y;
    const int n0 = blockIdx.x * 64;
    const int tid = threadIdx.x;
    const int tx = tid & 15, ty = tid >> 4;
    const float* A = g_hs + (size_t)t * HID * BATCH;

    ull acc[2][4];
    #pragma unroll
    for (int i = 0; i < 2; i++)
        #pragma unroll
        for (int n = 0; n < 4; n++) acc[i][n] = 0ull;

    const int rr = tid >> 2;           // o row for W staging
    const int kq = (tid & 3) << 2;
    const int obase = (rr >> 2) * 12 + (rr & 3) * 2;
    const int akk = tid >> 4, ac4 = (tid & 15) * 4;

    for (int k0 = 0; k0 < HID; k0 += 16) {
        *(float4*)&As2[akk][ac4] = *(const float4*)(A + (size_t)(k0 + akk) * BATCH + ac4);
        {
            float4 v = *(const float4*)(Wout + (size_t)(n0 + rr) * HID + k0 + kq);
            *(float2*)&Wsw[(kq + 0) * 196 + obase] = make_float2(v.x, v.x);
            *(float2*)&Wsw[(kq + 1) * 196 + obase] = make_float2(v.y, v.y);
            *(float2*)&Wsw[(kq + 2) * 196 + obase] = make_float2(v.z, v.z);
            *(float2*)&Wsw[(kq + 3) * 196 + obase] = make_float2(v.w, v.w);
        }
        __syncthreads();
        #pragma unroll
        for (int kk = 0; kk < 16; kk++) {
            ulonglong2 a = *(const ulonglong2*)&As2[kk][ty * 4];
            const float* wp = Wsw + kk * 196 + tx * 12;
            ulonglong2 w01 = *(const ulonglong2*)wp;
            ulonglong2 w23 = *(const ulonglong2*)(wp + 4);
            ffma2(acc[0][0], a.x, w01.x); ffma2(acc[1][0], a.y, w01.x);
            ffma2(acc[0][1], a.x, w01.y); ffma2(acc[1][1], a.y, w01.y);
            ffma2(acc[0][2], a.x, w23.x); ffma2(acc[1][2], a.y, w23.x);
            ffma2(acc[0][3], a.x, w23.y); ffma2(acc[1][3], a.y, w23.y);
        }
        __syncthreads();
    }

    float4 bb = *(const float4*)(bout + n0 + tx * 4);
    float2 u[2][4];
    #pragma unroll
    for (int p = 0; p < 2; p++)
        #pragma unroll
        for (int n = 0; n < 4; n++) u[p][n] = unpack2(acc[p][n]);
    #pragma unroll
    for (int bi = 0; bi < 4; bi++) {
        int p = bi >> 1;
        float4 r;
        if (bi & 1) r = make_float4(u[p][0].y + bb.x, u[p][1].y + bb.y,
                                    u[p][2].y + bb.z, u[p][3].y + bb.w);
        else        r = make_float4(u[p][0].x + bb.x, u[p][1].x + bb.y,
                                    u[p][2].x + bb.z, u[p][3].x + bb.w);
        *(float4*)(out + ((size_t)t * BATCH + ty * 4 + bi) * OUT_DIM + n0 + tx * 4) = r;
    }
}

// ================= persistent recurrent kernel =================
// 128 CTAs x 256 threads. FMA role: hk=tid>>6 (K-slice), s=tid&63 -> (ii,bg).
// Epilogue role: every thread owns one (col jj, batch bo) output.
__device__ __forceinline__ void loadh8(ulonglong2* hb, const float* p) {
    #pragma unroll
    for (int i = 0; i < 8; i++)
        hb[i] = __ldg((const ulonglong2*)(p + (size_t)i * BATCH));
}
__device__ __forceinline__ void comp8(ull acc[4][2], const ulonglong2* hb,
                                      const float* wb0, int kl) {
    #pragma unroll
    for (int q = 0; q < 4; q++) {
        const float* wr = wb0 + q * 4 * SW2_STRIDE + 2 * kl;
        ulonglong2 w0 = *(const ulonglong2*)(wr);
        ulonglong2 w1 = *(const ulonglong2*)(wr + 4);
        ulonglong2 w2 = *(const ulonglong2*)(wr + 8);
        ulonglong2 w3 = *(const ulonglong2*)(wr + 12);
        ffma2(acc[q][0], hb[0].x, w0.x); ffma2(acc[q][1], hb[0].y, w0.x);
        ffma2(acc[q][0], hb[1].x, w0.y); ffma2(acc[q][1], hb[1].y, w0.y);
        ffma2(acc[q][0], hb[2].x, w1.x); ffma2(acc[q][1], hb[2].y, w1.x);
        ffma2(acc[q][0], hb[3].x, w1.y); ffma2(acc[q][1], hb[3].y, w1.y);
        ffma2(acc[q][0], hb[4].x, w2.x); ffma2(acc[q][1], hb[4].y, w2.x);
        ffma2(acc[q][0], hb[5].x, w2.y); ffma2(acc[q][1], hb[5].y, w2.y);
        ffma2(acc[q][0], hb[6].x, w3.x); ffma2(acc[q][1], hb[6].y, w3.x);
        ffma2(acc[q][0], hb[7].x, w3.y); ffma2(acc[q][1], hb[7].y, w3.y);
    }
}

__global__ void __launch_bounds__(256, 1)
lstm_recurrent(const float* __restrict__ W_hh, float* __restrict__ out)
{
    extern __shared__ float smem[];
    float* sW2  = smem;                 // 16 x SW2_STRIDE (splatted weights)
    float* sRed = smem + SW2_FLOATS;    // 4 slices x 64 x 68

    const int tid = threadIdx.x;
    const int j0  = blockIdx.x << 2;
    // FMA role
    const int hk  = tid >> 6;
    const int s   = tid & 63;
    const int ii  = s >> 4;
    const int bg  = (s & 15) << 2;
    // epilogue role
    const int jj  = tid >> 6;           // column index 0..3
    const int bo  = tid & 63;           // batch
    const int j_out = j0 + jj;
    const int s2  = jj * 16 + (bo >> 2);
    const int bb2 = bo & 3;

    // stage W_hh pre-splatted
    #pragma unroll
    for (int u = 0; u < 8; u++) {
        int f4 = u * 256 + tid;
        int rr = f4 >> 7;
        int kk = (f4 & 127) << 2;
        int q = rr >> 2, iw = rr & 3;
        float4 v = *(const float4*)(W_hh + (size_t)(q * HID + j0 + iw) * HID + kk);
        float* d = sW2 + rr * SW2_STRIDE + 2 * kk;
        *(float4*)(d    ) = make_float4(v.x, v.x, v.y, v.y);
        *(float4*)(d + 4) = make_float4(v.z, v.z, v.w, v.w);
    }
    __syncthreads();

    float creg = 0.f;
    const float* wb0 = sW2 + ii * SW2_STRIDE + hk * 256;
    unsigned* barp = &g_bar;

    for (int t = 0; t < T_STEPS; t++) {
        // xg for this thread's output (issued early; DRAM latency hidden by FMA loop)
        float xg[4];
        #pragma unroll
        for (int q = 0; q < 4; q++)
            xg[q] = __ldg(g_xg + ((size_t)t * G4 + q * HID + j_out) * BATCH + bo);

        ull acc[4][2];
        #pragma unroll
        for (int q = 0; q < 4; q++) { acc[q][0] = 0ull; acc[q][1] = 0ull; }

        if (t > 0) {
            const float* hsrc = g_hs + ((size_t)(t - 1) * HID + hk * 128) * BATCH + bg;
            ulonglong2 hb0[8], hb1[8];
            loadh8(hb0, hsrc);
            #pragma unroll 2
            for (int g2 = 0; g2 < 8; g2++) {
                loadh8(hb1, hsrc + (size_t)(2 * g2 + 1) * 8 * BATCH);
                comp8(acc, hb0, wb0, 2 * g2 * 8);
                loadh8(hb0, hsrc + (size_t)(2 * g2 + 2) * 8 * BATCH);  // tail overread stays in-array
                comp8(acc, hb1, wb0, (2 * g2 + 1) * 8);
            }
        }

        // all slices publish partials: [hk][s][batch-in-quad][gate]
        {
            float2 lo[4], hi[4];
            #pragma unroll
            for (int q = 0; q < 4; q++) { lo[q] = unpack2(acc[q][0]); hi[q] = unpack2(acc[q][1]); }
            float* p = sRed + hk * SRED_SLICE + s * 68;
            *(float4*)(p + 0)  = make_float4(lo[0].x, lo[1].x, lo[2].x, lo[3].x);
            *(float4*)(p + 4)  = make_float4(lo[0].y, lo[1].y, lo[2].y, lo[3].y);
            *(float4*)(p + 8)  = make_float4(hi[0].x, hi[1].x, hi[2].x, hi[3].x);
            *(float4*)(p + 12) = make_float4(hi[0].y, hi[1].y, hi[2].y, hi[3].y);
        }
        __syncthreads();

        // epilogue: one output per thread
        {
            const float* rp = sRed + s2 * 68 + bb2 * 4;
            float4 v0 = *(const float4*)(rp);
            float4 v1 = *(const float4*)(rp + SRED_SLICE);
            float4 v2 = *(const float4*)(rp + 2 * SRED_SLICE);
            float4 v3 = *(const float4*)(rp + 3 * SRED_SLICE);
            float g0 = v0.x + v1.x + v2.x + v3.x + xg[0];
            float g1 = v0.y + v1.y + v2.y + v3.y + xg[1];
            float g2 = v0.z + v1.z + v2.z + v3.z + xg[2];
            float g3 = v0.w + v1.w + v2.w + v3.w + xg[3];
            float iv = sigf(g0);
            float fv = sigf(g1);
            float gv = tanhfast(g2);
            float ov = sigf(g3);
            creg = fv * creg + iv * gv;
            float hn = ov * tanhfast(creg);
            g_hs[((size_t)t * HID + j_out) * BATCH + bo] = hn;
            if (t == T_STEPS - 1) {
                out[OFF_H + (size_t)bo * HID + j_out] = hn;
                out[OFF_C + (size_t)bo * HID + j_out] = creg;
            }
        }

        // grid barrier: release arrive + acquire spin (tid 0), then CTA sync
        if (tid == 0) {
            unsigned target = (unsigned)(t + 1) * NCTA;
            asm volatile("red.release.gpu.global.add.u32 [%0], %1;"
                         :: "l"(barp), "r"(1u) : "memory");
            unsigned v;
            do {
                asm volatile("ld.acquire.gpu.global.u32 %0, [%1];"
                             : "=r"(v) : "l"(barp) : "memory");
            } while (v < target);
        }
        __syncthreads();
    }
}

extern "C" void kernel_launch(void* const* d_in, const int* in_sizes, int n_in,
                              void* d_out, int out_size) {
    const float* inputs = (const float*)d_in[0];
    const float* W_ih   = (const float*)d_in[1];
    const float* W_hh   = (const float*)d_in[2];
    const float* b_ih   = (const float*)d_in[3];
    const float* b_hh   = (const float*)d_in[4];
    const float* W_out  = (const float*)d_in[5];
    const float* b_out  = (const float*)d_in[6];
    float* out = (float*)d_out;

    reset_kernel<<<16, 256>>>(b_ih, b_hh);

    gemm_xgate<<<dim3(G4 / 128, T_STEPS), 256>>>(inputs, W_ih);

    cudaFuncSetAttribute(lstm_recurrent,
                         cudaFuncAttributeMaxDynamicSharedMemorySize, RSMEM_BYTES);
    lstm_recurrent<<<NCTA, 256, RSMEM_BYTES>>>(W_hh, out);

    gemm_out<<<dim3(OUT_DIM / 64, T_STEPS), 256>>>(W_out, b_out, out);
}